// round 14
// baseline (speedup 1.0000x reference)
#include <cuda_runtime.h>

#define N_FULL   50000
#define NLAT     10
#define MU       32
#define BATCH    8
#define NODES    32
#define MSTR     33               // m-stride in G/W2
#define ISTR     1058             // i-stride (mod 32 == 2 -> bank gets 2i term)
#define GSZ      (NLAT * ISTR)    // 10580 floats per array
#define TMAIN    512
#define TPREP    512

// smem float offsets (main)
#define OFF_G     0
#define OFF_W2    10580
#define OFF_P2    21160            // [8][10][33] = 2640
#define OFF_CM    23800            // int[10][32] = 320
#define SMEM_BYTES ((23800 + 320) * 4)   // 96,480 B -> 2 CTAs/SM

// Scratch (static __device__ arrays: no dynamic allocation allowed)
__device__ float g_encoded[NLAT * BATCH];                 // k-major [i*8+b], bias added
__device__ __align__(128) float g_dec4[N_FULL * 16];      // 64B rows [v0..v9,pad6]

// ---------------------------------------------------------------------------
// Kernel 1 (fused, 512 threads): blocks 0..79 compute encoded[b,i]+enc_b[i]
// (written k-major). Blocks 80..177 transpose decoder [n,N] -> [N,16].
// ---------------------------------------------------------------------------
__global__ void __launch_bounds__(TPREP)
prep_encode_kernel(const float* __restrict__ x,
                   const float* __restrict__ ew,
                   const float* __restrict__ enc_b,
                   const float* __restrict__ decoder) {
    if (blockIdx.x < BATCH * NLAT) {
        const int b = blockIdx.x / NLAT;
        const int i = blockIdx.x % NLAT;
        const float4* xr = (const float4*)(x  + (size_t)b * N_FULL);
        const float4* wr = (const float4*)(ew + (size_t)i * N_FULL);
        float acc = 0.0f;
#pragma unroll 4
        for (int t = threadIdx.x; t < N_FULL / 4; t += TPREP) {
            float4 a = __ldg(xr + t);
            float4 c = __ldg(wr + t);
            acc = fmaf(a.x, c.x, acc);
            acc = fmaf(a.y, c.y, acc);
            acc = fmaf(a.z, c.z, acc);
            acc = fmaf(a.w, c.w, acc);
        }
#pragma unroll
        for (int d = 16; d > 0; d >>= 1)
            acc += __shfl_xor_sync(0xffffffffu, acc, d);
        __shared__ float red[16];
        int lane = threadIdx.x & 31, warp = threadIdx.x >> 5;
        if (lane == 0) red[warp] = acc;
        __syncthreads();
        if (threadIdx.x == 0) {
            float s = 0.0f;
#pragma unroll
            for (int w = 0; w < 16; w++) s += red[w];
            g_encoded[i * 8 + b] = s + __ldg(enc_b + i);    // k-major store
        }
    } else {
        int p = (blockIdx.x - BATCH * NLAT) * TPREP + threadIdx.x;
        if (p < N_FULL) {
            float v[NLAT];
#pragma unroll
            for (int i = 0; i < NLAT; i++)
                v[i] = __ldg(decoder + (size_t)i * N_FULL + p);
            float4* dst = (float4*)(g_dec4 + (size_t)p * 16);
            dst[0] = make_float4(v[0], v[1], v[2], v[3]);
            dst[1] = make_float4(v[4], v[5], v[6], v[7]);
            dst[2] = make_float4(v[8], v[9], 0.0f, 0.0f);
            dst[3] = make_float4(0.0f, 0.0f, 0.0f, 0.0f);
        }
    }
}

// ---------------------------------------------------------------------------
// Kernel 2: main. 512 threads, 32 nodes/block, 2 CTAs/SM, 4 barriers.
//
//  CONCURRENT entry (no barrier):
//   - warps 0..9 (i = warp, j = lane): bw prefetch, z[b] from __ldg-broadcast
//     k-major g_encoded, inv2[b] kept in REGISTERS, cnt -> smem cm[i][j].
//   - warps 10..15: SPECULATIVE gather of all rows m<16 (always-safe subset;
//     cnt>=16 typically): nb via direct coalesced LDG, 4 lanes per 64B
//     decoder row -> 1 L1 wavefront/row. Gather overlaps phase-0 math.
//  B1. Residual gather (all 16 warps, 2 nodes each): rows m in [16, rmax_j),
//      rmax_j = max_i cm[i][j] + 1 (+1 guards the rsqrt cnt in phase C).
//  B2. Scan (warps 0..9): fully-unrolled 32-iter prefix; rows beyond rmax
//      hold garbage but are never read (cnt-1 < rmax).
//  B3. Phase C (warps 0..9): cnt = floor(rsqrt(inv2))+1;
//      smoothed = (Pg[cnt-1] - inv2*Pm2[cnt-1]) / (cnt - inv2*S2(cnt));
//      contribution enc[b,i]*smv -> P2[b][i][j].
//  B4. Combine (warps 0..7): sum P2 over i, store out[b,p].
// ---------------------------------------------------------------------------
__global__ void __launch_bounds__(TMAIN, 2)
main_kernel(const float* __restrict__ bw,
            const int*   __restrict__ neigh,
            float*       __restrict__ out) {
    extern __shared__ float sm[];
    float* G  = sm + OFF_G;
    float* W2 = sm + OFF_W2;
    float* P2 = sm + OFF_P2;
    int*   cm = (int*)(sm + OFF_CM);

    const int tid    = threadIdx.x;
    const int lane   = tid & 31;
    const int warp   = tid >> 5;
    const int p_base = blockIdx.x * NODES;
    const int q  = lane & 3;             // 16B quarter of 64B decoder row
    const int rl = lane >> 2;            // row-in-instruction 0..7

    float inv2r[BATCH];                  // registers, phase 0 -> phase C
    float encbi0 = 0.f, encbi1 = 0.f, encbi2 = 0.f, encbi3 = 0.f,
          encbi4 = 0.f, encbi5 = 0.f, encbi6 = 0.f, encbi7 = 0.f;

    if (warp >= NLAT) {
        // ---- speculative gather: rows m<16, chunks of 8 over 6 warps ----
#pragma unroll
        for (int t = 0; t < 11; t++) {
            const int c = (warp - NLAT) + 6 * t;     // 0..63
            if (c < 64) {
                const int j  = c >> 1;
                const int m  = (c & 1) * 8 + rl;
                const int pj = min(p_base + j, N_FULL - 1);
                const int nb = __ldg(neigh + (size_t)pj * MU + m);
                if (q < 3) {
                    float4 v = __ldg((const float4*)g_dec4 + nb * 4 + q);
                    const int a0 = (4 * q) * ISTR + m * MSTR + j;
                    G[a0] = v.x;
                    G[a0 + ISTR] = v.y;
                    if (q < 2) {
                        G[a0 + 2 * ISTR] = v.z;
                        G[a0 + 3 * ISTR] = v.w;
                    }
                }
            }
        }
    } else {
        // ---- phase 0: i = warp, j = lane ----
        const int i  = warp;
        const int pc = min(p_base + lane, N_FULL - 1);
        float bwv[NLAT];
#pragma unroll
        for (int k = 0; k < NLAT; k++)
            bwv[k] = __ldg(bw + (size_t)(i * NLAT + k) * N_FULL + pc);

        float z[BATCH];
#pragma unroll
        for (int b = 0; b < BATCH; b++) z[b] = 0.0f;
#pragma unroll
        for (int k = 0; k < NLAT; k++) {
            float4 e0 = __ldg((const float4*)g_encoded + k * 2);
            float4 e1 = __ldg((const float4*)g_encoded + k * 2 + 1);
            if (k == i) {   // stash enc[b][i] for phase C
                encbi0 = e0.x; encbi1 = e0.y; encbi2 = e0.z; encbi3 = e0.w;
                encbi4 = e1.x; encbi5 = e1.y; encbi6 = e1.z; encbi7 = e1.w;
            }
            z[0] = fmaf(bwv[k], e0.x, z[0]);
            z[1] = fmaf(bwv[k], e0.y, z[1]);
            z[2] = fmaf(bwv[k], e0.z, z[2]);
            z[3] = fmaf(bwv[k], e0.w, z[3]);
            z[4] = fmaf(bwv[k], e1.x, z[4]);
            z[5] = fmaf(bwv[k], e1.y, z[5]);
            z[6] = fmaf(bwv[k], e1.z, z[6]);
            z[7] = fmaf(bwv[k], e1.w, z[7]);
        }
        int cmax = 0;
#pragma unroll
        for (int b = 0; b < BATCH; b++) {
            float e    = __expf(-z[b]);
            float tt   = 1.0f + e;                              // = 1/w
            float u    = __fdividef((float)MU, tt);             // = MU*w
            int   cnt  = min(MU, (int)u + 1);
            inv2r[b]   = tt * tt * (1.0f / (float)(MU * MU));   // 1/(MU*w)^2
            cmax = max(cmax, cnt);
        }
        cm[i * 32 + lane] = cmax;
    }
    __syncthreads();                                   // B1

    // ---- residual gather: rows m in [16, rmax_j), warp = 2 nodes ----
    {
#pragma unroll
        for (int half = 0; half < 2; half++) {
            const int j = warp * 2 + half;
            int rmj = 0;
#pragma unroll
            for (int i = 0; i < NLAT; i++)
                rmj = max(rmj, cm[i * 32 + j]);        // broadcast LDS
            rmj = min(MU, rmj + 1);                    // +1 rsqrt guard
            if (rmj > 16) {
                const int pj = min(p_base + j, N_FULL - 1);
#pragma unroll
                for (int t4 = 2; t4 < 4; t4++) {
                    const int m = t4 * 8 + rl;
                    if (m < rmj && q < 3) {
                        const int nb = __ldg(neigh + (size_t)pj * MU + m);
                        float4 v = __ldg((const float4*)g_dec4 + nb * 4 + q);
                        const int a0 = (4 * q) * ISTR + m * MSTR + j;
                        G[a0] = v.x;
                        G[a0 + ISTR] = v.y;
                        if (q < 2) {
                            G[a0 + 2 * ISTR] = v.z;
                            G[a0 + 3 * ISTR] = v.w;
                        }
                    }
                }
            }
        }
    }
    __syncthreads();                                   // B2

    // ---- scan: warps 0..9 (i = warp, j = lane), fully unrolled ----
    if (warp < NLAT) {
        const int base = warp * ISTR + lane;
        float pg = 0.0f, pm = 0.0f;
#pragma unroll
        for (int m = 0; m < MU; m++) {
            float v = G[base + m * MSTR];
            pg += v;
            pm = fmaf((float)(m * m), v, pm);
            G [base + m * MSTR] = pg;
            W2[base + m * MSTR] = pm;
        }
    }
    __syncthreads();                                   // B3

    // ---- phase C: warps 0..9 (i = warp, j = lane) ----
    if (warp < NLAT) {
        const int i = warp, j = lane;
        float encbi[BATCH] = {encbi0, encbi1, encbi2, encbi3,
                              encbi4, encbi5, encbi6, encbi7};
#pragma unroll
        for (int b = 0; b < BATCH; b++) {
            float inv2 = inv2r[b];
            float u    = rsqrtf(inv2);                          // = MU*w
            int   cnt  = min(MU, (int)u + 1);                   // <= rmax_j

            const int base = i * ISTR + (cnt - 1) * MSTR + j;
            float Pg = G[base];
            float Pm = W2[base];
            int   c1 = cnt - 1;
            float S2 = (float)(c1 * cnt * (2 * cnt - 1)) * (1.0f / 6.0f);
            float s  = (float)cnt - inv2 * S2;
            float smv = __fdividef(fmaf(-inv2, Pm, Pg), s);
            P2[(b * NLAT + i) * MSTR + j] = encbi[b] * smv;
        }
    }
    __syncthreads();                                   // B4

    // ---- combine: warps 0..7 (b = warp, j = lane) ----
    const int p = p_base + lane;
    if (warp < BATCH && p < N_FULL) {
        float acc = 0.0f;
#pragma unroll
        for (int i = 0; i < NLAT; i++)
            acc += P2[(warp * NLAT + i) * MSTR + lane];
        out[(size_t)warp * N_FULL + p] = acc;
    }
}

// ---------------------------------------------------------------------------
extern "C" void kernel_launch(void* const* d_in, const int* in_sizes, int n_in,
                              void* d_out, int out_size) {
    const float* x       = (const float*)d_in[0];
    const float* enc_w   = (const float*)d_in[1];
    const float* enc_b   = (const float*)d_in[2];
    const float* decoder = (const float*)d_in[3];
    const float* bw      = (const float*)d_in[4];
    const int*   neigh   = (const int*)  d_in[5];
    float*       out     = (float*)d_out;
    (void)in_sizes; (void)n_in; (void)out_size;

    const int tp_blocks = (N_FULL + TPREP - 1) / TPREP;         // 98
    prep_encode_kernel<<<BATCH * NLAT + tp_blocks, TPREP>>>(x, enc_w, enc_b,
                                                            decoder);

    cudaFuncSetAttribute(main_kernel,
                         cudaFuncAttributeMaxDynamicSharedMemorySize,
                         SMEM_BYTES);
    main_kernel<<<(N_FULL + NODES - 1) / NODES, TMAIN, SMEM_BYTES>>>(
        bw, neigh, out);
}

// round 15
// speedup vs baseline: 1.3712x; 1.3712x over previous
#include <cuda_runtime.h>

#define N_FULL   50000
#define NLAT     10
#define MU       32
#define BATCH    8
#define NODES    32
#define MSTR     33               // m-stride in G/W2
#define ISTR     1058             // i-stride (mod 32 == 2 -> bank gets 2i term)
#define GSZ      (NLAT * ISTR)    // 10580 floats per array
#define TMAIN    512
#define TPREP    512

// smem float offsets (main)
#define OFF_G     0
#define OFF_W2    10580
#define OFF_P2    21160            // [8][10][33] = 2640
#define OFF_ENCS  23800            // [10][8] k-major = 80
#define OFF_INV2  23880            // [10][8][32] = 2560
#define OFF_CM    26440            // int[10][32] = 320
#define OFF_NB    26760            // ushort[1024]
#define SMEM_BYTES  (OFF_NB * 4 + NODES * MU * 2)   // 109,088 B -> 2 CTAs/SM

// Scratch (static __device__ arrays: no dynamic allocation allowed)
__device__ float g_encoded[BATCH * NLAT];                 // bias pre-added
__device__ __align__(128) float g_dec4[N_FULL * 16];      // 64B rows [v0..v9,pad6]

// ---------------------------------------------------------------------------
// Kernel 1 (fused, 512 threads): blocks 0..79 compute encoded[b,i]+enc_b[i].
// Blocks 80..177 transpose decoder [n,N] -> [N,16] (64B-aligned rows).
// ---------------------------------------------------------------------------
__global__ void __launch_bounds__(TPREP)
prep_encode_kernel(const float* __restrict__ x,
                   const float* __restrict__ ew,
                   const float* __restrict__ enc_b,
                   const float* __restrict__ decoder) {
    if (blockIdx.x < BATCH * NLAT) {
        const int b = blockIdx.x / NLAT;
        const int i = blockIdx.x % NLAT;
        const float4* xr = (const float4*)(x  + (size_t)b * N_FULL);
        const float4* wr = (const float4*)(ew + (size_t)i * N_FULL);
        float acc = 0.0f;
#pragma unroll 4
        for (int t = threadIdx.x; t < N_FULL / 4; t += TPREP) {
            float4 a = __ldg(xr + t);
            float4 c = __ldg(wr + t);
            acc = fmaf(a.x, c.x, acc);
            acc = fmaf(a.y, c.y, acc);
            acc = fmaf(a.z, c.z, acc);
            acc = fmaf(a.w, c.w, acc);
        }
#pragma unroll
        for (int d = 16; d > 0; d >>= 1)
            acc += __shfl_xor_sync(0xffffffffu, acc, d);
        __shared__ float red[16];
        int lane = threadIdx.x & 31, warp = threadIdx.x >> 5;
        if (lane == 0) red[warp] = acc;
        __syncthreads();
        if (threadIdx.x == 0) {
            float s = 0.0f;
#pragma unroll
            for (int w = 0; w < 16; w++) s += red[w];
            g_encoded[blockIdx.x] = s + __ldg(enc_b + i);   // bias folded in
        }
    } else {
        int p = (blockIdx.x - BATCH * NLAT) * TPREP + threadIdx.x;
        if (p < N_FULL) {
            float v[NLAT];
#pragma unroll
            for (int i = 0; i < NLAT; i++)
                v[i] = __ldg(decoder + (size_t)i * N_FULL + p);
            float4* dst = (float4*)(g_dec4 + (size_t)p * 16);
            dst[0] = make_float4(v[0], v[1], v[2], v[3]);
            dst[1] = make_float4(v[4], v[5], v[6], v[7]);
            dst[2] = make_float4(v[8], v[9], 0.0f, 0.0f);
            dst[3] = make_float4(0.0f, 0.0f, 0.0f, 0.0f);
        }
    }
}

// ---------------------------------------------------------------------------
// Kernel 2: main. 512 threads, 32 nodes/block, 2 CTAs/SM, 5 barriers.
//
//  Entry: NB tile -> smem (coalesced, all threads); warps 0..9 also issue
//    their 10 bw LDGs (independent, consumed after B0); encS fill.
//  Post-B0 OVERLAP:
//   - warps 10..15: gather chunks 0..35 (rows m<16; 6 shallow rounds each;
//     LDS nb from smem + independent LDG.128 -> no dependent global chains,
//     ~30 regs in flight, no spills).
//   - warps 0..9: phase 0 (z from bwv x encS, inv2 -> smem sInv2,
//     cm[i][j] = max cnt), then gather chunks 36..63 (<=3 rounds each).
//  B1. Residual gather (all warps, 2 nodes each): rows m in [16, rmax_j),
//      rmax_j = max_i cm[i][j] + 1 (guards the rsqrt cnt in phase C).
//  B2. Scan (warps 0..9): fully-unrolled 32-iter prefix (garbage beyond
//      rmax never read: cnt-1 < rmax).
//  B3. Phase C (warps 0..9): cnt = floor(rsqrt(inv2))+1;
//      smoothed = (Pg[cnt-1] - inv2*Pm2[cnt-1]) / (cnt - inv2*S2(cnt));
//      contribution enc[b,i]*smv -> P2[b][i][j].
//  B4. Combine (warps 0..7): sum P2 over i, store out[b,p].
// ---------------------------------------------------------------------------
__global__ void __launch_bounds__(TMAIN, 2)
main_kernel(const float* __restrict__ bw,
            const int*   __restrict__ neigh,
            float*       __restrict__ out) {
    extern __shared__ float sm[];
    float*          G     = sm + OFF_G;
    float*          W2    = sm + OFF_W2;
    float*          P2    = sm + OFF_P2;
    float*          encS  = sm + OFF_ENCS;
    float*          sInv2 = sm + OFF_INV2;
    int*            cm    = (int*)(sm + OFF_CM);
    unsigned short* NB    = (unsigned short*)(sm + OFF_NB);

    const int tid    = threadIdx.x;
    const int lane   = tid & 31;
    const int warp   = tid >> 5;
    const int p_base = blockIdx.x * NODES;
    const int q  = lane & 3;             // 16B quarter of 64B decoder row
    const int rl = lane >> 2;            // row-in-instruction 0..7

    // ---- entry: NB tile, bw prefetch (warps 0..9), encS ----
    {
        int base = p_base * MU + tid * 2;
        int2 v = make_int2(0, 0);
        if (base + 1 < N_FULL * MU) v = *(const int2*)(neigh + base);
        NB[tid * 2 + 0] = (unsigned short)v.x;
        NB[tid * 2 + 1] = (unsigned short)v.y;
    }
    float bwv[NLAT];
    const int pc = min(p_base + lane, N_FULL - 1);
    if (warp < NLAT) {
#pragma unroll
        for (int k = 0; k < NLAT; k++)
            bwv[k] = __ldg(bw + (size_t)(warp * NLAT + k) * N_FULL + pc);
    }
    if (tid < BATCH * NLAT)              // encS[k*8+b]
        encS[tid] = g_encoded[(tid & 7) * NLAT + (tid >> 3)];
    __syncthreads();                                   // B0

    // ---- overlapped: spec gather (m<16) + phase 0 ----
    if (warp >= NLAT) {
        // warps 10..15: chunks 0..35 (6 each). chunk c: j = c>>1, mb=(c&1)*8
#pragma unroll
        for (int r = 0; r < 6; r++) {
            const int c = (warp - NLAT) * 6 + r;
            const int j = c >> 1;
            const int m = (c & 1) * 8 + rl;
            const int nb = NB[j * MU + m];
            if (q < 3) {
                float4 v = __ldg((const float4*)g_dec4 + nb * 4 + q);
                const int a0 = (4 * q) * ISTR + m * MSTR + j;
                G[a0] = v.x;
                G[a0 + ISTR] = v.y;
                if (q < 2) {
                    G[a0 + 2 * ISTR] = v.z;
                    G[a0 + 3 * ISTR] = v.w;
                }
            }
        }
    } else {
        // warps 0..9: phase 0 (i = warp, j = lane)
        const int i = warp;
        float z[BATCH];
#pragma unroll
        for (int b = 0; b < BATCH; b++) z[b] = 0.0f;
#pragma unroll
        for (int k = 0; k < NLAT; k++) {
            float4 e0 = *(const float4*)(encS + k * 8);      // broadcast LDS
            float4 e1 = *(const float4*)(encS + k * 8 + 4);
            z[0] = fmaf(bwv[k], e0.x, z[0]);
            z[1] = fmaf(bwv[k], e0.y, z[1]);
            z[2] = fmaf(bwv[k], e0.z, z[2]);
            z[3] = fmaf(bwv[k], e0.w, z[3]);
            z[4] = fmaf(bwv[k], e1.x, z[4]);
            z[5] = fmaf(bwv[k], e1.y, z[5]);
            z[6] = fmaf(bwv[k], e1.z, z[6]);
            z[7] = fmaf(bwv[k], e1.w, z[7]);
        }
        int cmax = 0;
#pragma unroll
        for (int b = 0; b < BATCH; b++) {
            float e    = __expf(-z[b]);
            float tt   = 1.0f + e;                              // = 1/w
            float u    = __fdividef((float)MU, tt);             // = MU*w
            int   cnt  = min(MU, (int)u + 1);
            float inv2 = tt * tt * (1.0f / (float)(MU * MU));   // 1/(MU*w)^2
            sInv2[(i * 8 + b) * 32 + lane] = inv2;
            cmax = max(cmax, cnt);
        }
        cm[i * 32 + lane] = cmax;

        // then help with remaining spec chunks 36..63 (<=3 rounds)
#pragma unroll
        for (int r = 0; r < 3; r++) {
            const int c = 36 + warp + NLAT * r;
            if (c < 64) {
                const int j = c >> 1;
                const int m = (c & 1) * 8 + rl;
                const int nb = NB[j * MU + m];
                if (q < 3) {
                    float4 v = __ldg((const float4*)g_dec4 + nb * 4 + q);
                    const int a0 = (4 * q) * ISTR + m * MSTR + j;
                    G[a0] = v.x;
                    G[a0 + ISTR] = v.y;
                    if (q < 2) {
                        G[a0 + 2 * ISTR] = v.z;
                        G[a0 + 3 * ISTR] = v.w;
                    }
                }
            }
        }
    }
    __syncthreads();                                   // B1

    // ---- residual gather: rows m in [16, rmax_j), warp = 2 nodes ----
    {
#pragma unroll
        for (int half = 0; half < 2; half++) {
            const int j = warp * 2 + half;
            int rmj = 0;
#pragma unroll
            for (int i = 0; i < NLAT; i++)
                rmj = max(rmj, cm[i * 32 + j]);        // broadcast LDS
            rmj = min(MU, rmj + 1);                    // +1 rsqrt guard
            if (rmj > 16) {
#pragma unroll
                for (int t4 = 2; t4 < 4; t4++) {
                    const int m = t4 * 8 + rl;
                    if (m < rmj && q < 3) {
                        const int nb = NB[j * MU + m];
                        float4 v = __ldg((const float4*)g_dec4 + nb * 4 + q);
                        const int a0 = (4 * q) * ISTR + m * MSTR + j;
                        G[a0] = v.x;
                        G[a0 + ISTR] = v.y;
                        if (q < 2) {
                            G[a0 + 2 * ISTR] = v.z;
                            G[a0 + 3 * ISTR] = v.w;
                        }
                    }
                }
            }
        }
    }
    __syncthreads();                                   // B2

    // ---- scan: warps 0..9 (i = warp, j = lane), fully unrolled ----
    if (warp < NLAT) {
        const int base = warp * ISTR + lane;
        float pg = 0.0f, pm = 0.0f;
#pragma unroll
        for (int m = 0; m < MU; m++) {
            float v = G[base + m * MSTR];
            pg += v;
            pm = fmaf((float)(m * m), v, pm);
            G [base + m * MSTR] = pg;
            W2[base + m * MSTR] = pm;
        }
    }
    __syncthreads();                                   // B3

    // ---- phase C: warps 0..9 (i = warp, j = lane) ----
    if (warp < NLAT) {
        const int i = warp, j = lane;
#pragma unroll
        for (int b = 0; b < BATCH; b++) {
            float inv2 = sInv2[(i * 8 + b) * 32 + j];
            float u    = rsqrtf(inv2);                          // = MU*w
            int   cnt  = min(MU, (int)u + 1);                   // <= rmax_j

            const int base = i * ISTR + (cnt - 1) * MSTR + j;
            float Pg = G[base];
            float Pm = W2[base];
            int   c1 = cnt - 1;
            float S2 = (float)(c1 * cnt * (2 * cnt - 1)) * (1.0f / 6.0f);
            float s  = (float)cnt - inv2 * S2;
            float smv = __fdividef(fmaf(-inv2, Pm, Pg), s);
            P2[(b * NLAT + i) * MSTR + j] = encS[i * 8 + b] * smv;
        }
    }
    __syncthreads();                                   // B4

    // ---- combine: warps 0..7 (b = warp, j = lane) ----
    const int p = p_base + lane;
    if (warp < BATCH && p < N_FULL) {
        float acc = 0.0f;
#pragma unroll
        for (int i = 0; i < NLAT; i++)
            acc += P2[(warp * NLAT + i) * MSTR + lane];
        out[(size_t)warp * N_FULL + p] = acc;
    }
}

// ---------------------------------------------------------------------------
extern "C" void kernel_launch(void* const* d_in, const int* in_sizes, int n_in,
                              void* d_out, int out_size) {
    const float* x       = (const float*)d_in[0];
    const float* enc_w   = (const float*)d_in[1];
    const float* enc_b   = (const float*)d_in[2];
    const float* decoder = (const float*)d_in[3];
    const float* bw      = (const float*)d_in[4];
    const int*   neigh   = (const int*)  d_in[5];
    float*       out     = (float*)d_out;
    (void)in_sizes; (void)n_in; (void)out_size;

    const int tp_blocks = (N_FULL + TPREP - 1) / TPREP;         // 98
    prep_encode_kernel<<<BATCH * NLAT + tp_blocks, TPREP>>>(x, enc_w, enc_b,
                                                            decoder);

    cudaFuncSetAttribute(main_kernel,
                         cudaFuncAttributeMaxDynamicSharedMemorySize,
                         SMEM_BYTES);
    main_kernel<<<(N_FULL + NODES - 1) / NODES, TMAIN, SMEM_BYTES>>>(
        bw, neigh, out);
}